// round 3
// baseline (speedup 1.0000x reference)
#include <cuda_runtime.h>
#include <cuda_bf16.h>
#include <math.h>

// ---------------- constants ----------------
#define BATCH   128
#define DIM     384
#define RES     14
#define NPIX    196          // 14*14
#define KEY_DIM 32
#define NHEADS  12
#define NH_KD   384          // 32*12
#define DH      1536         // 4*32*12
#define HQKV    2304         // DH + 2*NH_KD
#define BN_EPS  1e-5f

// ---------------- scratch (device globals; no dynamic alloc allowed) -------
__device__ float g_qkv [ (size_t)BATCH * HQKV * NPIX ];   // 231 MB
__device__ float g_qdw [ (size_t)BATCH * NH_KD * NPIX ];  // 38.5 MB
__device__ float g_bias[ (size_t)NHEADS * NPIX * NPIX ];  // 1.8 MB
__device__ float g_p   [ (size_t)BATCH * NHEADS * NPIX * NPIX ]; // 236 MB
__device__ float g_att [ (size_t)BATCH * DH * NPIX ];     // 154 MB

// ---------------- K1/K6: NN GEMM + BN epilogue ------------------------------
// C[m][n] = BN(sum_k A[m][k] * B[k][n]);  A: [M,K] k-contig (weights, shared
// across batch), B: [K,N] n-contig (per batch), C: [M,N] per batch.
__global__ void gemm_nn_bn(const float* __restrict__ A,
                           const float* __restrict__ Bbase,
                           float* __restrict__ Cbase,
                           int M, int N, int K,
                           const float* __restrict__ bng,
                           const float* __restrict__ bnb,
                           const float* __restrict__ bnm,
                           const float* __restrict__ bnv,
                           int strideB, int strideC)
{
    const int b = blockIdx.z;
    const float* B = Bbase + (size_t)b * strideB;
    float*       C = Cbase + (size_t)b * strideC;

    __shared__ float As[64][16];
    __shared__ float Bs[16][64];

    const int tx = threadIdx.x & 15;
    const int ty = threadIdx.x >> 4;
    const int m0 = blockIdx.y * 64;
    const int n0 = blockIdx.x * 64;

    float acc[4][4];
#pragma unroll
    for (int i = 0; i < 4; i++)
#pragma unroll
        for (int j = 0; j < 4; j++) acc[i][j] = 0.f;

    for (int k0 = 0; k0 < K; k0 += 16) {
        // load A tile 64x16
        for (int l = threadIdx.x; l < 64 * 16; l += 256) {
            int r = l >> 4, c = l & 15;
            As[r][c] = A[(size_t)(m0 + r) * K + (k0 + c)]; // M,K multiples of tile
        }
        // load B tile 16x64 (guard n)
        for (int l = threadIdx.x; l < 16 * 64; l += 256) {
            int r = l >> 6, c = l & 63;
            int nn = n0 + c;
            Bs[r][c] = (nn < N) ? B[(size_t)(k0 + r) * N + nn] : 0.f;
        }
        __syncthreads();
#pragma unroll
        for (int kk = 0; kk < 16; kk++) {
            float a[4], bv[4];
#pragma unroll
            for (int i = 0; i < 4; i++) a[i] = As[ty * 4 + i][kk];
#pragma unroll
            for (int j = 0; j < 4; j++) bv[j] = Bs[kk][tx * 4 + j];
#pragma unroll
            for (int i = 0; i < 4; i++)
#pragma unroll
                for (int j = 0; j < 4; j++) acc[i][j] += a[i] * bv[j];
        }
        __syncthreads();
    }

#pragma unroll
    for (int i = 0; i < 4; i++) {
        int mm = m0 + ty * 4 + i;
        float s  = bng[mm] * rsqrtf(bnv[mm] + BN_EPS);
        float sh = bnb[mm] - bnm[mm] * s;
#pragma unroll
        for (int j = 0; j < 4; j++) {
            int nn = n0 + tx * 4 + j;
            if (nn < N) C[(size_t)mm * N + nn] = acc[i][j] * s + sh;
        }
    }
}

// ---------------- K2: depthwise 3x3 conv + BN -------------------------------
__global__ void dwconv_bn(const float* __restrict__ w,
                          const float* __restrict__ bng,
                          const float* __restrict__ bnb,
                          const float* __restrict__ bnm,
                          const float* __restrict__ bnv)
{
    int idx = blockIdx.x * 256 + threadIdx.x;
    if (idx >= BATCH * NH_KD * NPIX) return;
    int p  = idx % NPIX;
    int bc = idx / NPIX;
    int c  = bc % NH_KD;
    int b  = bc / NH_KD;
    int y = p / RES, x = p % RES;
    const float* src = g_qkv + (size_t)b * HQKV * NPIX + (size_t)c * NPIX;
    float acc = 0.f;
#pragma unroll
    for (int ky = 0; ky < 3; ky++) {
        int yy = y + ky - 1;
        if (yy < 0 || yy >= RES) continue;
#pragma unroll
        for (int kx = 0; kx < 3; kx++) {
            int xx = x + kx - 1;
            if (xx < 0 || xx >= RES) continue;
            acc += src[yy * RES + xx] * w[c * 9 + ky * 3 + kx];
        }
    }
    float s = bng[c] * rsqrtf(bnv[c] + BN_EPS);
    g_qdw[idx] = acc * s + (bnb[c] - bnm[c] * s);
}

// ---------------- K3: relative-position bias gather -------------------------
__global__ void bias_gather(const float* __restrict__ ab, const int* __restrict__ idxs)
{
    int idx = blockIdx.x * 256 + threadIdx.x;
    if (idx >= NHEADS * NPIX * NPIX) return;
    int h  = idx / (NPIX * NPIX);
    int ij = idx % (NPIX * NPIX);
    g_bias[idx] = ab[h * NPIX + idxs[ij]];
}

// ---------------- K4: QK^T * scale + bias, softmax --------------------------
// one CTA per (b,h). K staged in STATIC smem (28 KB, under 48KB limit — no
// attribute opt-in needed). Q held in registers (d = lane), broadcast via
// shfl. 8 query rows per warp per sweep.
__global__ void attn_softmax(void)
{
    const int h = blockIdx.x;
    const int b = blockIdx.y;
    __shared__ float k_s[32 * 224];    // [d][j] padded to 224, zero tail

    const float* qg = g_qdw + (size_t)b * NH_KD * NPIX + (size_t)h * KEY_DIM * NPIX;
    const float* kg = g_qkv + (size_t)b * HQKV * NPIX + (size_t)(NH_KD + h * KEY_DIM) * NPIX;

    for (int idx = threadIdx.x; idx < 32 * 224; idx += 256) {
        int d = idx / 224, j = idx % 224;
        k_s[idx] = (j < NPIX) ? kg[d * NPIX + j] : 0.f;
    }
    __syncthreads();

    const int w    = threadIdx.x >> 5;
    const int lane = threadIdx.x & 31;
    const float* bh = g_bias + (size_t)h * NPIX * NPIX;
    float* Pg = g_p + ((size_t)b * NHEADS + h) * NPIX * NPIX;
    const float scale = 0.17677669529663687f;   // 32^{-1/2}

    for (int i0 = w * 8; i0 < NPIX; i0 += 64) {
        // q rows i0..i0+7 for dim d = lane
        float q_reg[8];
#pragma unroll
        for (int r = 0; r < 8; r++) {
            int i = i0 + r;
            q_reg[r] = (i < NPIX) ? qg[(size_t)lane * NPIX + i] : 0.f;
        }

        float s[8][7];
#pragma unroll
        for (int r = 0; r < 8; r++)
#pragma unroll
            for (int m = 0; m < 7; m++) s[r][m] = 0.f;

        for (int d = 0; d < 32; d++) {
            float qv[8];
#pragma unroll
            for (int r = 0; r < 8; r++)
                qv[r] = __shfl_sync(0xffffffffu, q_reg[r], d);
#pragma unroll
            for (int m = 0; m < 7; m++) {
                float kv = k_s[d * 224 + lane + m * 32];
#pragma unroll
                for (int r = 0; r < 8; r++) s[r][m] += qv[r] * kv;
            }
        }

#pragma unroll
        for (int r = 0; r < 8; r++) {
            int i = i0 + r;
            if (i >= NPIX) break;
            float sv[7];
            float mx = -1e30f;
#pragma unroll
            for (int m = 0; m < 7; m++) {
                int j = lane + m * 32;
                float val = (j < NPIX) ? s[r][m] * scale + bh[(size_t)i * NPIX + j]
                                       : -1e30f;
                sv[m] = val;
                mx = fmaxf(mx, val);
            }
#pragma unroll
            for (int off = 16; off; off >>= 1)
                mx = fmaxf(mx, __shfl_xor_sync(0xffffffffu, mx, off));
            float sum = 0.f;
#pragma unroll
            for (int m = 0; m < 7; m++) {
                sv[m] = __expf(sv[m] - mx);   // invalid lanes -> 0
                sum += sv[m];
            }
#pragma unroll
            for (int off = 16; off; off >>= 1)
                sum += __shfl_xor_sync(0xffffffffu, sum, off);
            float inv = 1.f / sum;
#pragma unroll
            for (int m = 0; m < 7; m++) {
                int j = lane + m * 32;
                if (j < NPIX) Pg[(size_t)i * NPIX + j] = sv[m] * inv;
            }
        }
    }
}

// ---------------- K5: out = relu(V @ P^T)  (NT GEMM) -------------------------
// per (b,h): A = V [128][196] k-contig, B = P [196 rows i][196 k-contig j],
// C[d][i] = sum_j A[d][j]*B[i][j]
__global__ void gemm_nt_relu(void)
{
    const int z = blockIdx.z;
    const int b = z / NHEADS, h = z % NHEADS;
    const float* A = g_qkv + (size_t)b * HQKV * NPIX + (size_t)(2 * NH_KD + h * 128) * NPIX;
    const float* B = g_p + (size_t)z * NPIX * NPIX;
    float* C = g_att + (size_t)b * DH * NPIX + (size_t)h * 128 * NPIX;

    __shared__ float As[64][17];
    __shared__ float Bs[64][17];

    const int tx = threadIdx.x & 15;
    const int ty = threadIdx.x >> 4;
    const int m0 = blockIdx.y * 64;   // d
    const int n0 = blockIdx.x * 64;   // i

    float acc[4][4];
#pragma unroll
    for (int i = 0; i < 4; i++)
#pragma unroll
        for (int j = 0; j < 4; j++) acc[i][j] = 0.f;

    for (int k0 = 0; k0 < NPIX; k0 += 16) {
        for (int l = threadIdx.x; l < 64 * 16; l += 256) {
            int r = l >> 4, c = l & 15;
            int kk = k0 + c;
            As[r][c] = (kk < NPIX) ? A[(size_t)(m0 + r) * NPIX + kk] : 0.f;
        }
        for (int l = threadIdx.x; l < 64 * 16; l += 256) {
            int r = l >> 4, c = l & 15;
            int nn = n0 + r, kk = k0 + c;
            Bs[r][c] = (nn < NPIX && kk < NPIX) ? B[(size_t)nn * NPIX + kk] : 0.f;
        }
        __syncthreads();
#pragma unroll
        for (int kk = 0; kk < 16; kk++) {
            float a[4], bv[4];
#pragma unroll
            for (int i = 0; i < 4; i++) a[i] = As[ty * 4 + i][kk];
#pragma unroll
            for (int j = 0; j < 4; j++) bv[j] = Bs[tx * 4 + j][kk];
#pragma unroll
            for (int i = 0; i < 4; i++)
#pragma unroll
                for (int j = 0; j < 4; j++) acc[i][j] += a[i] * bv[j];
        }
        __syncthreads();
    }

#pragma unroll
    for (int i = 0; i < 4; i++) {
        int mm = m0 + ty * 4 + i;      // < 128 always
#pragma unroll
        for (int j = 0; j < 4; j++) {
            int nn = n0 + tx * 4 + j;
            if (nn < NPIX) C[(size_t)mm * NPIX + nn] = fmaxf(acc[i][j], 0.f);
        }
    }
}

// ---------------- launch ----------------------------------------------------
extern "C" void kernel_launch(void* const* d_in, const int* in_sizes, int n_in,
                              void* d_out, int out_size)
{
    const float* x      = (const float*)d_in[0];
    const float* qkv_w  = (const float*)d_in[1];
    const float* qkv_g  = (const float*)d_in[2];
    const float* qkv_b  = (const float*)d_in[3];
    const float* qkv_m  = (const float*)d_in[4];
    const float* qkv_v  = (const float*)d_in[5];
    const float* dw_w   = (const float*)d_in[6];
    const float* dw_g   = (const float*)d_in[7];
    const float* dw_b   = (const float*)d_in[8];
    const float* dw_m   = (const float*)d_in[9];
    const float* dw_v   = (const float*)d_in[10];
    const float* proj_w = (const float*)d_in[11];
    const float* proj_g = (const float*)d_in[12];
    const float* proj_b = (const float*)d_in[13];
    const float* proj_m = (const float*)d_in[14];
    const float* proj_v = (const float*)d_in[15];
    const float* ab     = (const float*)d_in[16];
    const int*   bidx   = (const int*)d_in[17];
    float* out = (float*)d_out;

    float* qkv; cudaGetSymbolAddress((void**)&qkv, g_qkv);
    float* att; cudaGetSymbolAddress((void**)&att, g_att);

    // K1: qkv = BN(W_qkv @ x)   per batch [2304 x 196 x 384]
    gemm_nn_bn<<<dim3(4, HQKV / 64, BATCH), 256>>>(
        qkv_w, x, qkv, HQKV, NPIX, DIM,
        qkv_g, qkv_b, qkv_m, qkv_v,
        DIM * NPIX, HQKV * NPIX);

    // K2: q <- BN(dwconv3x3(q))
    {
        int total = BATCH * NH_KD * NPIX;
        dwconv_bn<<<(total + 255) / 256, 256>>>(dw_w, dw_g, dw_b, dw_m, dw_v);
    }

    // K3: bias gather
    {
        int total = NHEADS * NPIX * NPIX;
        bias_gather<<<(total + 255) / 256, 256>>>(ab, bidx);
    }

    // K4: softmax(q^T k * scale + bias) -> P   (static smem, 28 KB)
    attn_softmax<<<dim3(NHEADS, BATCH), 256>>>();

    // K5: att = relu(V @ P^T)
    gemm_nt_relu<<<dim3(4, 2, BATCH * NHEADS), 256>>>();

    // K6: out = BN(W_proj @ att)  per batch [384 x 196 x 1536]
    gemm_nn_bn<<<dim3(4, DIM / 64, BATCH), 256>>>(
        proj_w, att, out, DIM, NPIX, DH,
        proj_g, proj_b, proj_m, proj_v,
        DH * NPIX, DIM * NPIX);
}

// round 5
// speedup vs baseline: 2.6001x; 2.6001x over previous
#include <cuda_runtime.h>
#include <cuda_bf16.h>
#include <math.h>
#include <stdint.h>

// ---------------- constants ----------------
#define BATCH   128
#define DIM     384
#define RES     14
#define NPIX    196
#define KEY_DIM 32
#define NHEADS  12
#define NH_KD   384
#define DH      1536
#define HQKV    2304
#define BN_EPS  1e-5f

// ---------------- scratch ----------------
__device__ float g_qkv [ (size_t)BATCH * HQKV * NPIX ];
__device__ float g_qdw [ (size_t)BATCH * NH_KD * NPIX ];
__device__ float g_bias[ (size_t)NHEADS * NPIX * NPIX ];
__device__ float g_p   [ (size_t)BATCH * NHEADS * NPIX * NPIX ];
__device__ float g_att [ (size_t)BATCH * DH * NPIX ];

// ---------------- helpers ----------------
__device__ __forceinline__ uint32_t smem_u32(const void* p) {
    uint32_t a;
    asm("{ .reg .u64 t; cvta.to.shared.u64 t, %1; cvt.u32.u64 %0, t; }"
        : "=r"(a) : "l"(p));
    return a;
}

#define LDSM4(r, addr) \
    asm volatile("ldmatrix.sync.aligned.m8n8.x4.shared.b16 {%0,%1,%2,%3}, [%4];" \
        : "=r"((r)[0]), "=r"((r)[1]), "=r"((r)[2]), "=r"((r)[3]) : "r"(addr))

#define MMA_BF16(d, a, bb) \
    asm volatile("mma.sync.aligned.m16n8k16.row.col.f32.bf16.bf16.f32 " \
        "{%0,%1,%2,%3}, {%4,%5,%6,%7}, {%8,%9}, {%0,%1,%2,%3};" \
        : "+f"((d)[0]), "+f"((d)[1]), "+f"((d)[2]), "+f"((d)[3]) \
        : "r"((a)[0]), "r"((a)[1]), "r"((a)[2]), "r"((a)[3]), \
          "r"((bb)[0]), "r"((bb)[1]))

// ================= warp-mma GEMM (bf16 hi/lo split, fp32 acc) =================
// C[m,n] = act(BN_m( sum_k A[m,k] * B[k,n] ))
// A: [M,K] k-contig.  B: TRANSB ? [K,N] n-contig : [N,K] k-contig.
// CTA tile 128x128, 8 warps (4m x 2n), warp tile 32x64, K-chunk 32.
template<bool TRANSB, bool HASBN, bool RELU>
__global__ void __launch_bounds__(256, 2)
gemm_mma(const float* __restrict__ Abase, const float* __restrict__ Bbase,
         float* __restrict__ Cbase, int N, int K, int nchunks,
         int lda, int ldb, int ldc,
         long aOuter, long aInner, int innerCnt,
         long bStride, long cStride,
         const float* __restrict__ bng, const float* __restrict__ bnb,
         const float* __restrict__ bnm, const float* __restrict__ bnv)
{
    constexpr int KPAD = 40;    // 80B row stride: 16B aligned, ldmatrix conflict-free
    __shared__ __align__(16) __nv_bfloat16 sA[2][128 * KPAD];  // [hi|lo]
    __shared__ __align__(16) __nv_bfloat16 sB[2][128 * KPAD];

    const int tid  = threadIdx.x;
    const int wid  = tid >> 5;
    const int lane = tid & 31;
    const int warp_m = wid & 3;       // 0..3 -> 32-row slices
    const int warp_n = wid >> 2;      // 0..1 -> 64-col slices

    const int n0 = blockIdx.x * 128;
    const int m0 = blockIdx.y * 128;
    const int z  = blockIdx.z;
    const int zb = z / innerCnt, zi = z - zb * innerCnt;
    const float* Ag = Abase + (size_t)zb * aOuter + (size_t)zi * aInner;
    const float* Bg = Bbase + (size_t)z * bStride;
    float*       Cg = Cbase + (size_t)z * cStride;

    const uint32_t sAa = smem_u32(sA);
    const uint32_t sBa = smem_u32(sB);
    constexpr uint32_t LO_OFF = 128 * KPAD * 2;   // bytes from hi to lo plane

    float acc[2][8][4];
#pragma unroll
    for (int t = 0; t < 2; t++)
#pragma unroll
        for (int j = 0; j < 8; j++)
#pragma unroll
            for (int c = 0; c < 4; c++) acc[t][j][c] = 0.f;

    for (int ch = 0; ch < nchunks; ch++) {
        const int k0 = ch * 32;

        // ---- stage A chunk [128 x 32] -> hi/lo bf16
#pragma unroll
        for (int i = 0; i < 4; i++) {
            int e   = (i * 256 + tid) << 2;
            int row = e >> 5;
            int k   = e & 31;
            float v[4];
            if (k0 + k + 3 < K) {
                float4 tv = *(const float4*)(Ag + (size_t)(m0 + row) * lda + k0 + k);
                v[0] = tv.x; v[1] = tv.y; v[2] = tv.z; v[3] = tv.w;
            } else {
#pragma unroll
                for (int j = 0; j < 4; j++)
                    v[j] = (k0 + k + j < K) ? Ag[(size_t)(m0 + row) * lda + k0 + k + j] : 0.f;
            }
            uint64_t hp = 0, lp = 0;
#pragma unroll
            for (int j = 0; j < 4; j++) {
                __nv_bfloat16 h = __float2bfloat16(v[j]);
                __nv_bfloat16 l = __float2bfloat16(v[j] - __bfloat162float(h));
                hp |= (uint64_t)__bfloat16_as_ushort(h) << (16 * j);
                lp |= (uint64_t)__bfloat16_as_ushort(l) << (16 * j);
            }
            *(uint64_t*)((char*)sA[0] + (size_t)(row * KPAD + k) * 2) = hp;
            *(uint64_t*)((char*)sA[1] + (size_t)(row * KPAD + k) * 2) = lp;
        }

        // ---- stage B chunk -> sB[n][k] hi/lo
        if (TRANSB) {
            // B[k][n] n-contig: coalesced read, transposed scalar store
#pragma unroll
            for (int i = 0; i < 16; i++) {
                int e = i * 256 + tid;
                int n = e & 127;
                int k = e >> 7;
                float v = 0.f;
                if ((n0 + n) < N && (k0 + k) < K)
                    v = Bg[(size_t)(k0 + k) * ldb + n0 + n];
                __nv_bfloat16 h = __float2bfloat16(v);
                __nv_bfloat16 l = __float2bfloat16(v - __bfloat162float(h));
                sB[0][n * KPAD + k] = h;
                sB[1][n * KPAD + k] = l;
            }
        } else {
            // B[n][k] k-contig: vectorized
#pragma unroll
            for (int i = 0; i < 4; i++) {
                int e = (i * 256 + tid) << 2;
                int n = e >> 5;
                int k = e & 31;
                float v[4];
                bool nok = (n0 + n) < N;
                if (nok && (k0 + k + 3 < K)) {
                    float4 tv = *(const float4*)(Bg + (size_t)(n0 + n) * ldb + k0 + k);
                    v[0] = tv.x; v[1] = tv.y; v[2] = tv.z; v[3] = tv.w;
                } else {
#pragma unroll
                    for (int j = 0; j < 4; j++)
                        v[j] = (nok && (k0 + k + j < K))
                             ? Bg[(size_t)(n0 + n) * ldb + k0 + k + j] : 0.f;
                }
                uint64_t hp = 0, lp = 0;
#pragma unroll
                for (int j = 0; j < 4; j++) {
                    __nv_bfloat16 h = __float2bfloat16(v[j]);
                    __nv_bfloat16 l = __float2bfloat16(v[j] - __bfloat162float(h));
                    hp |= (uint64_t)__bfloat16_as_ushort(h) << (16 * j);
                    lp |= (uint64_t)__bfloat16_as_ushort(l) << (16 * j);
                }
                *(uint64_t*)((char*)sB[0] + (size_t)(n * KPAD + k) * 2) = hp;
                *(uint64_t*)((char*)sB[1] + (size_t)(n * KPAD + k) * 2) = lp;
            }
        }

        __syncthreads();

        // ---- compute: 2 k16 steps x (hi*hi + lo*hi + hi*lo)
#pragma unroll
        for (int ks = 0; ks < 2; ks++) {
            const int kel = ks * 16;

            uint32_t a_hi[2][4], a_lo[2][4];
#pragma unroll
            for (int t = 0; t < 2; t++) {
                int row = warp_m * 32 + t * 16 + (lane & 15);
                int col = kel + ((lane >> 4) << 3);
                uint32_t ad = sAa + (uint32_t)(row * KPAD + col) * 2;
                LDSM4(a_hi[t], ad);
                LDSM4(a_lo[t], ad + LO_OFF);
            }

            int nrow = warp_n * 64 + (lane & 7) + ((lane >> 4) << 3);
            int bcol = kel + (((lane >> 3) & 1) << 3);
            uint32_t bd = sBa + (uint32_t)(nrow * KPAD + bcol) * 2;

            uint32_t b[8][2];
#pragma unroll
            for (int j = 0; j < 4; j++) {
                uint32_t r[4];
                LDSM4(r, bd + (uint32_t)(j * 16 * KPAD) * 2);
                b[2 * j][0] = r[0]; b[2 * j][1] = r[1];
                b[2 * j + 1][0] = r[2]; b[2 * j + 1][1] = r[3];
            }
            // hi*hi and lo*hi
#pragma unroll
            for (int t = 0; t < 2; t++)
#pragma unroll
                for (int j = 0; j < 8; j++) MMA_BF16(acc[t][j], a_hi[t], b[j]);
#pragma unroll
            for (int t = 0; t < 2; t++)
#pragma unroll
                for (int j = 0; j < 8; j++) MMA_BF16(acc[t][j], a_lo[t], b[j]);

            // reload b with lo plane; hi*lo
#pragma unroll
            for (int j = 0; j < 4; j++) {
                uint32_t r[4];
                LDSM4(r, bd + LO_OFF + (uint32_t)(j * 16 * KPAD) * 2);
                b[2 * j][0] = r[0]; b[2 * j][1] = r[1];
                b[2 * j + 1][0] = r[2]; b[2 * j + 1][1] = r[3];
            }
#pragma unroll
            for (int t = 0; t < 2; t++)
#pragma unroll
                for (int j = 0; j < 8; j++) MMA_BF16(acc[t][j], a_hi[t], b[j]);
        }
        __syncthreads();
    }

    // ---- epilogue: BN/relu, float2 stores
#pragma unroll
    for (int t = 0; t < 2; t++) {
        int r0 = m0 + warp_m * 32 + t * 16 + (lane >> 2);
        int r1 = r0 + 8;
        float s0 = 1.f, h0 = 0.f, s1 = 1.f, h1 = 0.f;
        if constexpr (HASBN) {
            float a = bng[r0] * rsqrtf(bnv[r0] + BN_EPS);
            s0 = a; h0 = bnb[r0] - bnm[r0] * a;
            float c = bng[r1] * rsqrtf(bnv[r1] + BN_EPS);
            s1 = c; h1 = bnb[r1] - bnm[r1] * c;
        }
#pragma unroll
        for (int j = 0; j < 8; j++) {
            int nn = n0 + warp_n * 64 + j * 8 + 2 * (lane & 3);
            if (nn < N) {
                float v0 = acc[t][j][0] * s0 + h0;
                float v1 = acc[t][j][1] * s0 + h0;
                float v2 = acc[t][j][2] * s1 + h1;
                float v3 = acc[t][j][3] * s1 + h1;
                if (RELU) {
                    v0 = fmaxf(v0, 0.f); v1 = fmaxf(v1, 0.f);
                    v2 = fmaxf(v2, 0.f); v3 = fmaxf(v3, 0.f);
                }
                float2 p0 = make_float2(v0, v1);
                float2 p1 = make_float2(v2, v3);
                *(float2*)(Cg + (size_t)r0 * ldc + nn) = p0;
                *(float2*)(Cg + (size_t)r1 * ldc + nn) = p1;
            }
        }
    }
}

// ---------------- K2: depthwise 3x3 conv + BN -------------------------------
__global__ void dwconv_bn(const float* __restrict__ w,
                          const float* __restrict__ bng,
                          const float* __restrict__ bnb,
                          const float* __restrict__ bnm,
                          const float* __restrict__ bnv)
{
    int idx = blockIdx.x * 256 + threadIdx.x;
    if (idx >= BATCH * NH_KD * NPIX) return;
    int p  = idx % NPIX;
    int bc = idx / NPIX;
    int c  = bc % NH_KD;
    int b  = bc / NH_KD;
    int y = p / RES, x = p % RES;
    const float* src = g_qkv + (size_t)b * HQKV * NPIX + (size_t)c * NPIX;
    float acc = 0.f;
#pragma unroll
    for (int ky = 0; ky < 3; ky++) {
        int yy = y + ky - 1;
        if (yy < 0 || yy >= RES) continue;
#pragma unroll
        for (int kx = 0; kx < 3; kx++) {
            int xx = x + kx - 1;
            if (xx < 0 || xx >= RES) continue;
            acc += src[yy * RES + xx] * w[c * 9 + ky * 3 + kx];
        }
    }
    float s = bng[c] * rsqrtf(bnv[c] + BN_EPS);
    g_qdw[idx] = acc * s + (bnb[c] - bnm[c] * s);
}

// ---------------- K3: relative-position bias gather -------------------------
__global__ void bias_gather(const float* __restrict__ ab, const int* __restrict__ idxs)
{
    int idx = blockIdx.x * 256 + threadIdx.x;
    if (idx >= NHEADS * NPIX * NPIX) return;
    int h  = idx / (NPIX * NPIX);
    int ij = idx % (NPIX * NPIX);
    g_bias[idx] = ab[h * NPIX + idxs[ij]];
}

// ---------------- K4: QK^T * scale + bias, softmax ---------------------------
__global__ void attn_softmax(void)
{
    const int h = blockIdx.x;
    const int b = blockIdx.y;
    __shared__ float k_s[32 * 224];

    const float* qg = g_qdw + (size_t)b * NH_KD * NPIX + (size_t)h * KEY_DIM * NPIX;
    const float* kg = g_qkv + (size_t)b * HQKV * NPIX + (size_t)(NH_KD + h * KEY_DIM) * NPIX;

    for (int idx = threadIdx.x; idx < 32 * 224; idx += 256) {
        int d = idx / 224, j = idx % 224;
        k_s[idx] = (j < NPIX) ? kg[d * NPIX + j] : 0.f;
    }
    __syncthreads();

    const int w    = threadIdx.x >> 5;
    const int lane = threadIdx.x & 31;
    const float* bh = g_bias + (size_t)h * NPIX * NPIX;
    float* Pg = g_p + ((size_t)b * NHEADS + h) * NPIX * NPIX;
    const float scale = 0.17677669529663687f;

    for (int i0 = w * 8; i0 < NPIX; i0 += 64) {
        float q_reg[8];
#pragma unroll
        for (int r = 0; r < 8; r++) {
            int i = i0 + r;
            q_reg[r] = (i < NPIX) ? qg[(size_t)lane * NPIX + i] : 0.f;
        }

        float s[8][7];
#pragma unroll
        for (int r = 0; r < 8; r++)
#pragma unroll
            for (int m = 0; m < 7; m++) s[r][m] = 0.f;

        for (int d = 0; d < 32; d++) {
            float qv[8];
#pragma unroll
            for (int r = 0; r < 8; r++)
                qv[r] = __shfl_sync(0xffffffffu, q_reg[r], d);
#pragma unroll
            for (int m = 0; m < 7; m++) {
                float kv = k_s[d * 224 + lane + m * 32];
#pragma unroll
                for (int r = 0; r < 8; r++) s[r][m] += qv[r] * kv;
            }
        }

#pragma unroll
        for (int r = 0; r < 8; r++) {
            int i = i0 + r;
            if (i >= NPIX) break;
            float sv[7];
            float mx = -1e30f;
#pragma unroll
            for (int m = 0; m < 7; m++) {
                int j = lane + m * 32;
                float val = (j < NPIX) ? s[r][m] * scale + bh[(size_t)i * NPIX + j]
                                       : -1e30f;
                sv[m] = val;
                mx = fmaxf(mx, val);
            }
#pragma unroll
            for (int off = 16; off; off >>= 1)
                mx = fmaxf(mx, __shfl_xor_sync(0xffffffffu, mx, off));
            float sum = 0.f;
#pragma unroll
            for (int m = 0; m < 7; m++) {
                sv[m] = __expf(sv[m] - mx);
                sum += sv[m];
            }
#pragma unroll
            for (int off = 16; off; off >>= 1)
                sum += __shfl_xor_sync(0xffffffffu, sum, off);
            float inv = 1.f / sum;
#pragma unroll
            for (int m = 0; m < 7; m++) {
                int j = lane + m * 32;
                if (j < NPIX) Pg[(size_t)i * NPIX + j] = sv[m] * inv;
            }
        }
    }
}

// ---------------- launch ----------------------------------------------------
extern "C" void kernel_launch(void* const* d_in, const int* in_sizes, int n_in,
                              void* d_out, int out_size)
{
    const float* x      = (const float*)d_in[0];
    const float* qkv_w  = (const float*)d_in[1];
    const float* qkv_g  = (const float*)d_in[2];
    const float* qkv_b  = (const float*)d_in[3];
    const float* qkv_m  = (const float*)d_in[4];
    const float* qkv_v  = (const float*)d_in[5];
    const float* dw_w   = (const float*)d_in[6];
    const float* dw_g   = (const float*)d_in[7];
    const float* dw_b   = (const float*)d_in[8];
    const float* dw_m   = (const float*)d_in[9];
    const float* dw_v   = (const float*)d_in[10];
    const float* proj_w = (const float*)d_in[11];
    const float* proj_g = (const float*)d_in[12];
    const float* proj_b = (const float*)d_in[13];
    const float* proj_m = (const float*)d_in[14];
    const float* proj_v = (const float*)d_in[15];
    const float* ab     = (const float*)d_in[16];
    const int*   bidx   = (const int*)d_in[17];
    float* out = (float*)d_out;

    float* qkv; cudaGetSymbolAddress((void**)&qkv, g_qkv);
    float* att; cudaGetSymbolAddress((void**)&att, g_att);
    float* pmat; cudaGetSymbolAddress((void**)&pmat, g_p);

    // K1: qkv = BN(W_qkv @ x)   [2304 x 196, K=384] per batch
    gemm_mma<true, true, false><<<dim3(2, HQKV / 128, BATCH), 256>>>(
        qkv_w, x, qkv,
        NPIX, DIM, DIM / 32,
        DIM, NPIX, NPIX,
        0L, 0L, 1,
        (long)DIM * NPIX, (long)HQKV * NPIX,
        qkv_g, qkv_b, qkv_m, qkv_v);

    // K2: q <- BN(dwconv3x3(q))
    {
        int total = BATCH * NH_KD * NPIX;
        dwconv_bn<<<(total + 255) / 256, 256>>>(dw_w, dw_g, dw_b, dw_m, dw_v);
    }

    // K3: bias gather
    {
        int total = NHEADS * NPIX * NPIX;
        bias_gather<<<(total + 255) / 256, 256>>>(ab, bidx);
    }

    // K4: softmax(q^T k * scale + bias) -> P
    attn_softmax<<<dim3(NHEADS, BATCH), 256>>>();

    // K5: att = relu(V @ P^T)   [128 x 196, K=196] per (b,h)
    gemm_mma<false, false, true><<<dim3(2, 1, BATCH * NHEADS), 256>>>(
        qkv + (size_t)2 * NH_KD * NPIX, pmat, att,
        NPIX, NPIX, (NPIX + 31) / 32,
        NPIX, NPIX, NPIX,
        (long)HQKV * NPIX, (long)128 * NPIX, NHEADS,
        (long)NPIX * NPIX, (long)128 * NPIX,
        nullptr, nullptr, nullptr, nullptr);

    // K6: out = BN(W_proj @ att)   [384 x 196, K=1536] per batch
    gemm_mma<true, true, false><<<dim3(2, DIM / 128, BATCH), 256>>>(
        proj_w, att, out,
        NPIX, DH, DH / 32,
        DH, NPIX, NPIX,
        0L, 0L, 1,
        (long)DH * NPIX, (long)DIM * NPIX,
        proj_g, proj_b, proj_m, proj_v);
}

// round 6
// speedup vs baseline: 3.6289x; 1.3957x over previous
#include <cuda_runtime.h>
#include <cuda_bf16.h>
#include <math.h>
#include <stdint.h>

// ---------------- constants ----------------
#define BATCH   128
#define DIM     384
#define RES     14
#define NPIX    196
#define KEY_DIM 32
#define NHEADS  12
#define NH_KD   384
#define DH      1536
#define HQKV    2304
#define BN_EPS  1e-5f
#define NPAD    208     // NPIX padded to mult of 16

// ---------------- scratch ----------------
__device__ float g_qkv [ (size_t)BATCH * 768 * NPIX ];            // q+k fp32 only
__device__ float g_qdw [ (size_t)BATCH * NH_KD * NPIX ];
__device__ float g_bias[ (size_t)NHEADS * NPIX * NPIX ];

__device__ __nv_bfloat16 g_qw_h[ HQKV * DIM ],  g_qw_l[ HQKV * DIM ];
__device__ __nv_bfloat16 g_pw_h[ DIM * DH ],    g_pw_l[ DIM * DH ];
__device__ __nv_bfloat16 g_xT_h[ (size_t)BATCH * NPIX * DIM ],  g_xT_l[ (size_t)BATCH * NPIX * DIM ];
__device__ __nv_bfloat16 g_v_h [ (size_t)BATCH * DH * NPAD ],   g_v_l [ (size_t)BATCH * DH * NPAD ];
__device__ __nv_bfloat16 g_p_h [ (size_t)BATCH * NHEADS * NPIX * NPAD ],
                         g_p_l [ (size_t)BATCH * NHEADS * NPIX * NPAD ];
__device__ __nv_bfloat16 g_at_h[ (size_t)BATCH * NPIX * DH ],   g_at_l[ (size_t)BATCH * NPIX * DH ];

// ---------------- helpers ----------------
__device__ __forceinline__ uint32_t smem_u32(const void* p) {
    uint32_t a;
    asm("{ .reg .u64 t; cvta.to.shared.u64 t, %1; cvt.u32.u64 %0, t; }"
        : "=r"(a) : "l"(p));
    return a;
}
#define LDSM4(r, addr) \
    asm volatile("ldmatrix.sync.aligned.m8n8.x4.shared.b16 {%0,%1,%2,%3}, [%4];" \
        : "=r"((r)[0]), "=r"((r)[1]), "=r"((r)[2]), "=r"((r)[3]) : "r"(addr))
#define MMA_BF16(d, a, bb) \
    asm volatile("mma.sync.aligned.m16n8k16.row.col.f32.bf16.bf16.f32 " \
        "{%0,%1,%2,%3}, {%4,%5,%6,%7}, {%8,%9}, {%0,%1,%2,%3};" \
        : "+f"((d)[0]), "+f"((d)[1]), "+f"((d)[2]), "+f"((d)[3]) \
        : "r"((a)[0]), "r"((a)[1]), "r"((a)[2]), "r"((a)[3]), \
          "r"((bb)[0]), "r"((bb)[1]))
#define CP_ASYNC16(dst, src, sz) \
    asm volatile("cp.async.cg.shared.global [%0], [%1], 16, %2;" \
                 :: "r"(dst), "l"(src), "r"(sz))
#define CP_COMMIT() asm volatile("cp.async.commit_group;" ::: "memory")
#define CP_WAIT(n)  asm volatile("cp.async.wait_group %0;" :: "n"(n) : "memory")

__device__ __forceinline__ void split_bf16(float v, __nv_bfloat16& h, __nv_bfloat16& l) {
    h = __float2bfloat16(v);
    l = __float2bfloat16(v - __bfloat162float(h));
}

// ================= pipelined bf16-plane GEMM =================
// C[m,n] = act(BN_m( sum_k A[m,k]*B[n,k] ))  -- both operands k-contig planes.
// CTA 128x128, 8 warps (4m x 2n), K-chunk 16, 2-stage cp.async.
// OUTMODE: 0 = fp32 out; 1 = fp32 if m0<mSplit else bf16 planes (pad cols zeroed);
//          2 = transposed bf16 planes  C^T[n][zi*128 + m]  (K5 -> attT).
template<int OUTMODE, bool HASBN, bool RELU>
__global__ void __launch_bounds__(256, 2)
gemm_bf16(const __nv_bfloat16* __restrict__ Ah, const __nv_bfloat16* __restrict__ Al,
          const __nv_bfloat16* __restrict__ Bh, const __nv_bfloat16* __restrict__ Bl,
          float* __restrict__ Cf, __nv_bfloat16* __restrict__ Ch, __nv_bfloat16* __restrict__ Cl,
          int nchunks, int lda, int ldb,
          long aOuter, long aInner, int innerCnt,
          long bStride, long cfStride, long cpStride,
          int ldcF, int ldcP, int nrowsB, int mSplit,
          const float* __restrict__ bng, const float* __restrict__ bnb,
          const float* __restrict__ bnm, const float* __restrict__ bnv)
{
    constexpr int KP = 24;
    constexpr uint32_t PL = 128 * KP * 2;          // plane bytes
    __shared__ __align__(16) __nv_bfloat16 smbuf[2 * 4 * 128 * KP];  // 49152 B

    const int tid  = threadIdx.x;
    const int wid  = tid >> 5;
    const int lane = tid & 31;
    const int warp_m = wid & 3;
    const int warp_n = wid >> 2;
    const int n0 = blockIdx.x * 128;
    const int m0 = blockIdx.y * 128;
    const int z  = blockIdx.z;
    const int zb = z / innerCnt, zi = z - zb * innerCnt;

    const __nv_bfloat16* Agh = Ah + (size_t)zb * aOuter + (size_t)zi * aInner + (size_t)m0 * lda;
    const __nv_bfloat16* Agl = Al + (size_t)zb * aOuter + (size_t)zi * aInner + (size_t)m0 * lda;
    const __nv_bfloat16* Bgh = Bh + (size_t)z * bStride;
    const __nv_bfloat16* Bgl = Bl + (size_t)z * bStride;

    const uint32_t smb = smem_u32(smbuf);

    // --- staging lambda: 4 x cp.async 16B per thread per chunk
    auto stage = [&](int ch, int s) {
        const int k0 = ch * 16;
#pragma unroll
        for (int i = 0; i < 4; i++) {
            int c    = i * 256 + tid;
            int p    = c >> 8;           // plane 0..3
            int row  = (c >> 1) & 127;
            int half = c & 1;
            uint32_t dst = smb + (uint32_t)(s * 4 + p) * PL + (uint32_t)(row * KP + half * 8) * 2;
            const __nv_bfloat16* src;
            unsigned sz = 16;
            if (p < 2) {
                src = (p == 0 ? Agh : Agl) + (size_t)row * lda + k0 + half * 8;
            } else {
                int rowg = n0 + row;
                bool ok = rowg < nrowsB;
                if (!ok) { rowg = 0; sz = 0; }
                src = (p == 2 ? Bgh : Bgl) + (size_t)rowg * ldb + k0 + half * 8;
            }
            CP_ASYNC16(dst, src, sz);
        }
        CP_COMMIT();
    };

    float acc[2][8][4];
#pragma unroll
    for (int t = 0; t < 2; t++)
#pragma unroll
        for (int j = 0; j < 8; j++)
#pragma unroll
            for (int c = 0; c < 4; c++) acc[t][j][c] = 0.f;

    stage(0, 0);

    for (int ch = 0; ch < nchunks; ch++) {
        const int s = ch & 1;
        if (ch + 1 < nchunks) { stage(ch + 1, s ^ 1); CP_WAIT(1); }
        else                  { CP_WAIT(0); }
        __syncthreads();

        const uint32_t base = smb + (uint32_t)s * 4 * PL;
        const uint32_t aHi = base, aLo = base + PL, bHi = base + 2 * PL, bLo = base + 3 * PL;

        uint32_t a_hi[2][4], a_lo[2][4];
#pragma unroll
        for (int t = 0; t < 2; t++) {
            int row = warp_m * 32 + t * 16 + (lane & 15);
            int col = (lane >> 4) << 3;
            uint32_t off = (uint32_t)(row * KP + col) * 2;
            LDSM4(a_hi[t], aHi + off);
            LDSM4(a_lo[t], aLo + off);
        }
        int nrow = warp_n * 64 + (lane & 7) + ((lane >> 4) << 3);
        int bcol = ((lane >> 3) & 1) << 3;
        uint32_t boff = (uint32_t)(nrow * KP + bcol) * 2;

        uint32_t b[8][2];
#pragma unroll
        for (int j = 0; j < 4; j++) {
            uint32_t r[4];
            LDSM4(r, bHi + boff + (uint32_t)(j * 16 * KP) * 2);
            b[2 * j][0] = r[0]; b[2 * j][1] = r[1];
            b[2 * j + 1][0] = r[2]; b[2 * j + 1][1] = r[3];
        }
#pragma unroll
        for (int t = 0; t < 2; t++)
#pragma unroll
            for (int j = 0; j < 8; j++) MMA_BF16(acc[t][j], a_hi[t], b[j]);
#pragma unroll
        for (int t = 0; t < 2; t++)
#pragma unroll
            for (int j = 0; j < 8; j++) MMA_BF16(acc[t][j], a_lo[t], b[j]);
#pragma unroll
        for (int j = 0; j < 4; j++) {
            uint32_t r[4];
            LDSM4(r, bLo + boff + (uint32_t)(j * 16 * KP) * 2);
            b[2 * j][0] = r[0]; b[2 * j][1] = r[1];
            b[2 * j + 1][0] = r[2]; b[2 * j + 1][1] = r[3];
        }
#pragma unroll
        for (int t = 0; t < 2; t++)
#pragma unroll
            for (int j = 0; j < 8; j++) MMA_BF16(acc[t][j], a_hi[t], b[j]);

        __syncthreads();   // buffer reuse safety before next stage() overwrites
    }

    // ---------------- epilogues ----------------
    if (OUTMODE == 0 || OUTMODE == 1) {
        const bool isF32 = (OUTMODE == 0) || (m0 < mSplit);
#pragma unroll
        for (int t = 0; t < 2; t++) {
            int r0 = m0 + warp_m * 32 + t * 16 + (lane >> 2);
            int r1 = r0 + 8;
            float s0 = 1.f, h0 = 0.f, s1 = 1.f, h1 = 0.f;
            if (HASBN) {
                float a = bng[r0] * rsqrtf(bnv[r0] + BN_EPS);
                s0 = a; h0 = bnb[r0] - bnm[r0] * a;
                float c = bng[r1] * rsqrtf(bnv[r1] + BN_EPS);
                s1 = c; h1 = bnb[r1] - bnm[r1] * c;
            }
#pragma unroll
            for (int j = 0; j < 8; j++) {
                int nn = n0 + warp_n * 64 + j * 8 + 2 * (lane & 3);
                float v0 = acc[t][j][0] * s0 + h0;
                float v1 = acc[t][j][1] * s0 + h0;
                float v2 = acc[t][j][2] * s1 + h1;
                float v3 = acc[t][j][3] * s1 + h1;
                if (RELU) {
                    v0 = fmaxf(v0, 0.f); v1 = fmaxf(v1, 0.f);
                    v2 = fmaxf(v2, 0.f); v3 = fmaxf(v3, 0.f);
                }
                if (isF32) {
                    if (nn < NPIX) {
                        *(float2*)(Cf + (size_t)z * cfStride + (size_t)r0 * ldcF + nn) = make_float2(v0, v1);
                        *(float2*)(Cf + (size_t)z * cfStride + (size_t)r1 * ldcF + nn) = make_float2(v2, v3);
                    }
                } else {
                    if (nn < NPAD) {
                        if (nn >= NPIX) { v0 = v1 = v2 = v3 = 0.f; }
                        __nv_bfloat16 ha, la, hb, lb;
                        size_t p0 = (size_t)z * cpStride + (size_t)(r0 - mSplit) * ldcP + nn;
                        size_t p1 = (size_t)z * cpStride + (size_t)(r1 - mSplit) * ldcP + nn;
                        split_bf16(v0, ha, la); split_bf16(v1, hb, lb);
                        *(__nv_bfloat162*)(Ch + p0) = __nv_bfloat162(ha, hb);
                        *(__nv_bfloat162*)(Cl + p0) = __nv_bfloat162(la, lb);
                        split_bf16(v2, ha, la); split_bf16(v3, hb, lb);
                        *(__nv_bfloat162*)(Ch + p1) = __nv_bfloat162(ha, hb);
                        *(__nv_bfloat162*)(Cl + p1) = __nv_bfloat162(la, lb);
                    }
                }
            }
        }
    } else {
        // OUTMODE 2: transposed plane output via smem (reuse stage buffer)
        __nv_bfloat16* ep = smbuf;   // [128 i][136 d]
#pragma unroll
        for (int plane = 0; plane < 2; plane++) {
            __syncthreads();
#pragma unroll
            for (int t = 0; t < 2; t++) {
                int d0 = warp_m * 32 + t * 16 + (lane >> 2);
                int d1 = d0 + 8;
#pragma unroll
                for (int j = 0; j < 8; j++) {
                    int il = warp_n * 64 + j * 8 + 2 * (lane & 3);
                    float v[4];
#pragma unroll
                    for (int c = 0; c < 4; c++) {
                        float x = acc[t][j][c];
                        v[c] = RELU ? fmaxf(x, 0.f) : x;
                    }
                    __nv_bfloat16 o[4];
#pragma unroll
                    for (int c = 0; c < 4; c++) {
                        __nv_bfloat16 h = __float2bfloat16(v[c]);
                        o[c] = plane == 0 ? h : __float2bfloat16(v[c] - __bfloat162float(h));
                    }
                    ep[il * 136 + d0]       = o[0];
                    ep[(il + 1) * 136 + d0] = o[1];
                    ep[il * 136 + d1]       = o[2];
                    ep[(il + 1) * 136 + d1] = o[3];
                }
            }
            __syncthreads();
            __nv_bfloat16* dst = (plane == 0 ? Ch : Cl) + (size_t)zb * cpStride + (size_t)zi * 128;
            for (int c2 = tid; c2 < 2048; c2 += 256) {
                int row = c2 >> 4, off = (c2 & 15) * 8;
                int i = n0 + row;
                if (i < NPIX) {
                    uint4 val = *(uint4*)(ep + row * 136 + off);
                    *(uint4*)(dst + (size_t)i * ldcP + off) = val;
                }
            }
        }
    }
}

// ---------------- pre-convert kernels ----------------
__global__ void convert_weights(const float* __restrict__ qw, const float* __restrict__ pw)
{
    int i = blockIdx.x * 256 + threadIdx.x;
    if (i < HQKV * DIM) split_bf16(qw[i], g_qw_h[i], g_qw_l[i]);
    if (i < DIM * DH)   split_bf16(pw[i], g_pw_h[i], g_pw_l[i]);
}

__global__ void transpose_x(const float* __restrict__ x)
{
    __shared__ float t[32][33];
    int p0 = blockIdx.x * 32, c0 = blockIdx.y * 32, b = blockIdx.z;
    for (int r = threadIdx.y; r < 32; r += 8) {
        int p = p0 + threadIdx.x;
        t[r][threadIdx.x] = (p < NPIX) ? x[((size_t)b * DIM + c0 + r) * NPIX + p] : 0.f;
    }
    __syncthreads();
    for (int r = threadIdx.y; r < 32; r += 8) {
        int p = p0 + r, c = c0 + threadIdx.x;
        if (p < NPIX) {
            size_t o = ((size_t)b * NPIX + p) * DIM + c;
            split_bf16(t[threadIdx.x][r], g_xT_h[o], g_xT_l[o]);
        }
    }
}

// ---------------- dwconv + BN ----------------
__global__ void dwconv_bn(const float* __restrict__ w,
                          const float* __restrict__ bng,
                          const float* __restrict__ bnb,
                          const float* __restrict__ bnm,
                          const float* __restrict__ bnv)
{
    int idx = blockIdx.x * 256 + threadIdx.x;
    if (idx >= BATCH * NH_KD * NPIX) return;
    int p  = idx % NPIX;
    int bc = idx / NPIX;
    int c  = bc % NH_KD;
    int b  = bc / NH_KD;
    int y = p / RES, x = p % RES;
    const float* src = g_qkv + (size_t)b * 768 * NPIX + (size_t)c * NPIX;
    float acc = 0.f;
#pragma unroll
    for (int ky = 0; ky < 3; ky++) {
        int yy = y + ky - 1;
        if (yy < 0 || yy >= RES) continue;
#pragma unroll
        for (int kx = 0; kx < 3; kx++) {
            int xx = x + kx - 1;
            if (xx < 0 || xx >= RES) continue;
            acc += src[yy * RES + xx] * w[c * 9 + ky * 3 + kx];
        }
    }
    float s = bng[c] * rsqrtf(bnv[c] + BN_EPS);
    g_qdw[idx] = acc * s + (bnb[c] - bnm[c] * s);
}

// ---------------- bias gather ----------------
__global__ void bias_gather(const float* __restrict__ ab, const int* __restrict__ idxs)
{
    int idx = blockIdx.x * 256 + threadIdx.x;
    if (idx >= NHEADS * NPIX * NPIX) return;
    int h  = idx / (NPIX * NPIX);
    int ij = idx % (NPIX * NPIX);
    g_bias[idx] = ab[h * NPIX + idxs[ij]];
}

// ---------------- softmax: P written as bf16 hi/lo planes -------------------
__global__ void attn_softmax(void)
{
    const int h = blockIdx.x;
    const int b = blockIdx.y;
    __shared__ float k_s[32 * 224];

    const float* qg = g_qdw + (size_t)b * NH_KD * NPIX + (size_t)h * KEY_DIM * NPIX;
    const float* kg = g_qkv + (size_t)b * 768 * NPIX + (size_t)(NH_KD + h * KEY_DIM) * NPIX;

    for (int idx = threadIdx.x; idx < 32 * 224; idx += 256) {
        int d = idx / 224, j = idx % 224;
        k_s[idx] = (j < NPIX) ? kg[d * NPIX + j] : 0.f;
    }
    __syncthreads();

    const int w    = threadIdx.x >> 5;
    const int lane = threadIdx.x & 31;
    const float* bh = g_bias + (size_t)h * NPIX * NPIX;
    const size_t zoff = ((size_t)b * NHEADS + h) * NPIX * NPAD;
    const float scale = 0.17677669529663687f;

    for (int i0 = w * 8; i0 < NPIX; i0 += 64) {
        float q_reg[8];
#pragma unroll
        for (int r = 0; r < 8; r++) {
            int i = i0 + r;
            q_reg[r] = (i < NPIX) ? qg[(size_t)lane * NPIX + i] : 0.f;
        }

        float s[8][7];
#pragma unroll
        for (int r = 0; r < 8; r++)
#pragma unroll
            for (int m = 0; m < 7; m++) s[r][m] = 0.f;

        for (int d = 0; d < 32; d++) {
            float qv[8];
#pragma unroll
            for (int r = 0; r < 8; r++)
                qv[r] = __shfl_sync(0xffffffffu, q_reg[r], d);
#pragma unroll
            for (int m = 0; m < 7; m++) {
                float kv = k_s[d * 224 + lane + m * 32];
#pragma unroll
                for (int r = 0; r < 8; r++) s[r][m] += qv[r] * kv;
            }
        }

#pragma unroll
        for (int r = 0; r < 8; r++) {
            int i = i0 + r;
            if (i >= NPIX) break;
            float sv[7];
            float mx = -1e30f;
#pragma unroll
            for (int m = 0; m < 7; m++) {
                int j = lane + m * 32;
                float val = (j < NPIX) ? s[r][m] * scale + bh[(size_t)i * NPIX + j]
                                       : -1e30f;
                sv[m] = val;
                mx = fmaxf(mx, val);
            }
#pragma unroll
            for (int off = 16; off; off >>= 1)
                mx = fmaxf(mx, __shfl_xor_sync(0xffffffffu, mx, off));
            float sum = 0.f;
#pragma unroll
            for (int m = 0; m < 7; m++) {
                sv[m] = __expf(sv[m] - mx);
                sum += sv[m];
            }
#pragma unroll
            for (int off = 16; off; off >>= 1)
                sum += __shfl_xor_sync(0xffffffffu, sum, off);
            float inv = 1.f / sum;
#pragma unroll
            for (int m = 0; m < 7; m++) {
                int j = lane + m * 32;
                if (j < NPIX) {
                    float val = sv[m] * inv;
                    __nv_bfloat16 hh, ll;
                    split_bf16(val, hh, ll);
                    g_p_h[zoff + (size_t)i * NPAD + j] = hh;
                    g_p_l[zoff + (size_t)i * NPAD + j] = ll;
                } else if (j < NPAD) {
                    g_p_h[zoff + (size_t)i * NPAD + j] = __float2bfloat16(0.f);
                    g_p_l[zoff + (size_t)i * NPAD + j] = __float2bfloat16(0.f);
                }
            }
        }
    }
}

// ---------------- launch ----------------------------------------------------
extern "C" void kernel_launch(void* const* d_in, const int* in_sizes, int n_in,
                              void* d_out, int out_size)
{
    const float* x      = (const float*)d_in[0];
    const float* qkv_w  = (const float*)d_in[1];
    const float* qkv_g  = (const float*)d_in[2];
    const float* qkv_b  = (const float*)d_in[3];
    const float* qkv_m  = (const float*)d_in[4];
    const float* qkv_v  = (const float*)d_in[5];
    const float* dw_w   = (const float*)d_in[6];
    const float* dw_g   = (const float*)d_in[7];
    const float* dw_b   = (const float*)d_in[8];
    const float* dw_m   = (const float*)d_in[9];
    const float* dw_v   = (const float*)d_in[10];
    const float* proj_w = (const float*)d_in[11];
    const float* proj_g = (const float*)d_in[12];
    const float* proj_b = (const float*)d_in[13];
    const float* proj_m = (const float*)d_in[14];
    const float* proj_v = (const float*)d_in[15];
    const float* ab     = (const float*)d_in[16];
    const int*   bidx   = (const int*)d_in[17];
    float* out = (float*)d_out;

    float* qkvf;  cudaGetSymbolAddress((void**)&qkvf,  g_qkv);
    __nv_bfloat16 *qwh, *qwl, *pwh, *pwl, *xth, *xtl, *vh, *vl, *ph, *pl, *ath, *atl;
    cudaGetSymbolAddress((void**)&qwh, g_qw_h);  cudaGetSymbolAddress((void**)&qwl, g_qw_l);
    cudaGetSymbolAddress((void**)&pwh, g_pw_h);  cudaGetSymbolAddress((void**)&pwl, g_pw_l);
    cudaGetSymbolAddress((void**)&xth, g_xT_h);  cudaGetSymbolAddress((void**)&xtl, g_xT_l);
    cudaGetSymbolAddress((void**)&vh,  g_v_h);   cudaGetSymbolAddress((void**)&vl,  g_v_l);
    cudaGetSymbolAddress((void**)&ph,  g_p_h);   cudaGetSymbolAddress((void**)&pl,  g_p_l);
    cudaGetSymbolAddress((void**)&ath, g_at_h);  cudaGetSymbolAddress((void**)&atl, g_at_l);

    // P0: convert weights + transpose/convert x
    convert_weights<<<(HQKV * DIM + 255) / 256, 256>>>(qkv_w, proj_w);
    transpose_x<<<dim3(7, 12, BATCH), dim3(32, 8)>>>(x);

    // K1: qkv = BN(W_qkv @ x)  -> fp32 rows<768, V planes rows>=768
    gemm_bf16<1, true, false><<<dim3(2, HQKV / 128, BATCH), 256>>>(
        qwh, qwl, xth, xtl,
        qkvf, vh, vl,
        DIM / 16, DIM, DIM,
        0L, 0L, 1,
        (long)NPIX * DIM, (long)768 * NPIX, (long)DH * NPAD,
        NPIX, NPAD, NPIX, 768,
        qkv_g, qkv_b, qkv_m, qkv_v);

    // K2: q <- BN(dwconv3x3(q))
    {
        int total = BATCH * NH_KD * NPIX;
        dwconv_bn<<<(total + 255) / 256, 256>>>(dw_w, dw_g, dw_b, dw_m, dw_v);
    }
    // K3: bias gather
    {
        int total = NHEADS * NPIX * NPIX;
        bias_gather<<<(total + 255) / 256, 256>>>(ab, bidx);
    }
    // K4: softmax -> P planes
    attn_softmax<<<dim3(NHEADS, BATCH), 256>>>();

    // K5: attT planes = relu(V @ P^T)^T  (per b,h)
    gemm_bf16<2, false, true><<<dim3(2, 1, BATCH * NHEADS), 256>>>(
        vh, vl, ph, pl,
        nullptr, ath, atl,
        NPAD / 16, NPAD, NPAD,
        (long)DH * NPAD, (long)128 * NPAD, NHEADS,
        (long)NPIX * NPAD, 0L, (long)NPIX * DH,
        0, DH, NPIX, 0,
        nullptr, nullptr, nullptr, nullptr);

    // K6: out = BN(W_proj @ att)  (B = attT planes, k-contig)
    gemm_bf16<0, true, false><<<dim3(2, DIM / 128, BATCH), 256>>>(
        pwh, pwl, ath, atl,
        out, nullptr, nullptr,
        DH / 16, DH, DH,
        0L, 0L, 1,
        (long)NPIX * DH, (long)DIM * NPIX, 0L,
        NPIX, 0, NPIX, DIM,
        proj_g, proj_b, proj_m, proj_v);
}